// round 4
// baseline (speedup 1.0000x reference)
#include <cuda_runtime.h>

#define NN 64
#define CC 64
#define HH 128
#define WW 128
#define HWSZ (HH * WW)
#define OH 126
#define OW 126
#define OUT_ROWS_PER_TILE 16
#define N_TILES 8
#define TILE_ROWS 18          // 16 output rows + 2 halo
#define TILE_STRIDE 132       // padded row, keeps 16B alignment
#define SM_TILE (TILE_ROWS * TILE_STRIDE)
#define CP_PER_STAGE (TILE_ROWS * 32)   // 576 float4 copies

__device__ __forceinline__ void cp_async16(const float* smem, const float* gmem) {
    unsigned saddr = (unsigned)__cvta_generic_to_shared((void*)smem);
    asm volatile("cp.async.cg.shared.global [%0], [%1], 16;\n" :: "r"(saddr), "l"(gmem));
}
__device__ __forceinline__ void cp_commit() {
    asm volatile("cp.async.commit_group;\n" ::: "memory");
}
__device__ __forceinline__ void cp_wait2() {
    asm volatile("cp.async.wait_group 2;\n" ::: "memory");
}

// One channel of 3x3 conv on a 2-row x 4-col output patch.
__device__ __forceinline__ void compute_ch(const float* __restrict__ t,
                                           const float4* __restrict__ w4,
                                           float* __restrict__ acc) {
    const float4 wa = w4[0];
    const float4 wb = w4[1];
    const float w8  = ((const float*)(w4 + 2))[0];
    const float w0 = wa.x, w1 = wa.y, w2 = wa.z, w3 = wa.w;
    const float w4_ = wb.x, w5 = wb.y, w6 = wb.z, w7 = wb.w;

    #pragma unroll
    for (int j = 0; j < 4; ++j) {                 // 4 input rows -> 2 output rows
        const float* row = t + j * TILE_STRIDE;   // [reg+imm] addressing
        const float4 p = *(const float4*)(row);
        const float2 q = *(const float2*)(row + 4);
        const float v0 = p.x, v1 = p.y, v2 = p.z, v3 = p.w, v4 = q.x, v5 = q.y;
        #pragma unroll
        for (int kh = 0; kh < 3; ++kh) {
            const int ro = j - kh;                // compile-time after unroll
            if (ro >= 0 && ro < 2) {
                const float a = (kh == 0) ? w0 : (kh == 1) ? w3 : w6;
                const float b = (kh == 0) ? w1 : (kh == 1) ? w4_ : w7;
                const float cc = (kh == 0) ? w2 : (kh == 1) ? w5 : w8;
                acc[ro * 4 + 0] = fmaf(v0, a, acc[ro * 4 + 0]);
                acc[ro * 4 + 0] = fmaf(v1, b, acc[ro * 4 + 0]);
                acc[ro * 4 + 0] = fmaf(v2, cc, acc[ro * 4 + 0]);
                acc[ro * 4 + 1] = fmaf(v1, a, acc[ro * 4 + 1]);
                acc[ro * 4 + 1] = fmaf(v2, b, acc[ro * 4 + 1]);
                acc[ro * 4 + 1] = fmaf(v3, cc, acc[ro * 4 + 1]);
                acc[ro * 4 + 2] = fmaf(v2, a, acc[ro * 4 + 2]);
                acc[ro * 4 + 2] = fmaf(v3, b, acc[ro * 4 + 2]);
                acc[ro * 4 + 2] = fmaf(v4, cc, acc[ro * 4 + 2]);
                acc[ro * 4 + 3] = fmaf(v3, a, acc[ro * 4 + 3]);
                acc[ro * 4 + 3] = fmaf(v4, b, acc[ro * 4 + 3]);
                acc[ro * 4 + 3] = fmaf(v5, cc, acc[ro * 4 + 3]);
            }
        }
    }
}

__global__ __launch_bounds__(256, 4)
void imagewise_conv2d_kernel(const float* __restrict__ img,
                             const float* __restrict__ ker,
                             float* __restrict__ out) {
    __shared__ float4 wts4[CC * 3];                       // 12 floats / channel (padded)
    __shared__ __align__(16) float tile[4][SM_TILE];      // 4-stage ring

    const int n     = blockIdx.x;
    const int yt    = blockIdx.y;
    const int tid   = threadIdx.x;
    const int tx    = tid & 31;
    const int ty    = tid >> 5;
    const int x0    = tx * 4;
    const int y0    = ty * 2;
    const int ybase = yt * OUT_ROWS_PER_TILE;

    // ---- stage weights, padded so each channel is 3 float4s ----
    {
        const float* kn = ker + (size_t)n * CC * 9;
        for (int e = tid; e < CC * 9; e += 256) {
            int c = e / 9;
            int i = e - c * 9;
            ((float*)&wts4[c * 3])[i] = kn[e];
        }
    }

    // ---- hoisted copy descriptors (loop-invariant across channels) ----
    int soff[3], goff[3];
    #pragma unroll
    for (int k = 0; k < 3; ++k) {
        int idx = tid + k * 256;
        int r   = idx >> 5;
        int c4  = (idx & 31) * 4;
        int rg  = ybase + r; if (rg > HH - 1) rg = HH - 1;   // clamp halo
        soff[k] = r * TILE_STRIDE + c4;
        goff[k] = rg * WW + c4;
    }
    const int  soff0 = soff[0], soff1 = soff[1], soff2 = soff[2];
    const int  goff0 = goff[0], goff1 = goff[1], goff2 = goff[2];
    const bool has3  = (tid + 512) < CP_PER_STAGE;           // tid < 64

    const float* imgn = img + (size_t)n * CC * HWSZ;

    auto issue = [&](float* sbase, const float* g) {
        cp_async16(sbase + soff0, g + goff0);
        cp_async16(sbase + soff1, g + goff1);
        if (has3) cp_async16(sbase + soff2, g + goff2);
        cp_commit();
    };

    // ---- prologue: channels 0,1,2 into stages 0,1,2 ----
    const float* src = imgn;
    issue(&tile[0][0], src); src += HWSZ;
    issue(&tile[1][0], src); src += HWSZ;
    issue(&tile[2][0], src); src += HWSZ;     // src now -> channel 3

    float acc[8];
    #pragma unroll
    for (int i = 0; i < 8; ++i) acc[i] = 0.0f;

    const int yx = y0 * TILE_STRIDE + x0;
    const float4* wp = wts4;
    int ch = 0;

    // Steady state: wait ch done (2 newer in flight), sync, issue ch+3, compute ch.
    #define STEP(S)                                                         \
        do {                                                                \
            cp_wait2();                                                     \
            __syncthreads();                                                \
            if (ch + 3 < CC) { issue(&tile[(S + 3) & 3][0], src); src += HWSZ; } \
            else             { cp_commit(); }                               \
            compute_ch(&tile[S][yx], wp, acc);                              \
            wp += 3; ++ch;                                                  \
        } while (0)

    for (int cb = 0; cb < CC; cb += 4) {
        STEP(0); STEP(1); STEP(2); STEP(3);
    }
    #undef STEP

    // ---- store (mask 126-row/col edges) ----
    const int gy0 = ybase + y0;
    #pragma unroll
    for (int ry = 0; ry < 2; ++ry) {
        const int y = gy0 + ry;
        if (y < OH) {
            float* o = out + ((size_t)n * OH + y) * OW + x0;
            #pragma unroll
            for (int xc = 0; xc < 4; ++xc) {
                if (x0 + xc < OW) o[xc] = acc[ry * 4 + xc];
            }
        }
    }
}

extern "C" void kernel_launch(void* const* d_in, const int* in_sizes, int n_in,
                              void* d_out, int out_size) {
    const float* img = (const float*)d_in[0];   // [64,64,128,128] f32
    const float* ker = (const float*)d_in[1];   // [64,64,3,3]     f32
    float* out       = (float*)d_out;           // [64,1,126,126]  f32

    dim3 grid(NN, N_TILES);
    imagewise_conv2d_kernel<<<grid, 256>>>(img, ker, out);
}

// round 5
// speedup vs baseline: 1.7282x; 1.7282x over previous
#include <cuda_runtime.h>

#define NN 64
#define CC 64
#define HH 128
#define WW 128
#define HWSZ (HH * WW)
#define OH 126
#define OW 126
#define OUT_ROWS_PER_TILE 16
#define N_TILES 8
#define TILE_ROWS 18          // 16 output rows + 2 halo
#define TILE_STRIDE 132       // padded row, keeps 16B alignment
#define SM_TILE (TILE_ROWS * TILE_STRIDE)
#define STAGES 3
#define CP_PER_STAGE (TILE_ROWS * 32)   // 576 float4 copies

__device__ __forceinline__ void cp_async16(const float* smem, const float* gmem) {
    unsigned saddr = (unsigned)__cvta_generic_to_shared((void*)smem);
    asm volatile("cp.async.cg.shared.global [%0], [%1], 16;\n" :: "r"(saddr), "l"(gmem));
}
__device__ __forceinline__ void cp_commit() {
    asm volatile("cp.async.commit_group;\n" ::: "memory");
}
__device__ __forceinline__ void cp_wait1() {
    asm volatile("cp.async.wait_group 1;\n" ::: "memory");
}
__device__ __forceinline__ void cp_wait0() {
    asm volatile("cp.async.wait_group 0;\n" ::: "memory");
}

// One channel of 3x3 conv on a 2-row x 4-col output patch. Weights packed 3xfloat4.
__device__ __forceinline__ void compute_ch(const float* __restrict__ t,
                                           const float4* __restrict__ w4,
                                           float* __restrict__ acc) {
    const float4 wa = w4[0];
    const float4 wb = w4[1];
    const float w8  = ((const float*)(w4 + 2))[0];
    const float w0 = wa.x, w1 = wa.y, w2 = wa.z, w3 = wa.w;
    const float w4_ = wb.x, w5 = wb.y, w6 = wb.z, w7 = wb.w;

    #pragma unroll
    for (int j = 0; j < 4; ++j) {                 // 4 input rows -> 2 output rows
        const float* row = t + j * TILE_STRIDE;
        const float4 p = *(const float4*)(row);
        const float2 q = *(const float2*)(row + 4);
        const float v0 = p.x, v1 = p.y, v2 = p.z, v3 = p.w, v4 = q.x, v5 = q.y;
        #pragma unroll
        for (int kh = 0; kh < 3; ++kh) {
            const int ro = j - kh;                // compile-time after unroll
            if (ro >= 0 && ro < 2) {
                const float a  = (kh == 0) ? w0 : (kh == 1) ? w3 : w6;
                const float b  = (kh == 0) ? w1 : (kh == 1) ? w4_ : w7;
                const float cc = (kh == 0) ? w2 : (kh == 1) ? w5 : w8;
                acc[ro * 4 + 0] = fmaf(v0, a,  acc[ro * 4 + 0]);
                acc[ro * 4 + 0] = fmaf(v1, b,  acc[ro * 4 + 0]);
                acc[ro * 4 + 0] = fmaf(v2, cc, acc[ro * 4 + 0]);
                acc[ro * 4 + 1] = fmaf(v1, a,  acc[ro * 4 + 1]);
                acc[ro * 4 + 1] = fmaf(v2, b,  acc[ro * 4 + 1]);
                acc[ro * 4 + 1] = fmaf(v3, cc, acc[ro * 4 + 1]);
                acc[ro * 4 + 2] = fmaf(v2, a,  acc[ro * 4 + 2]);
                acc[ro * 4 + 2] = fmaf(v3, b,  acc[ro * 4 + 2]);
                acc[ro * 4 + 2] = fmaf(v4, cc, acc[ro * 4 + 2]);
                acc[ro * 4 + 3] = fmaf(v3, a,  acc[ro * 4 + 3]);
                acc[ro * 4 + 3] = fmaf(v4, b,  acc[ro * 4 + 3]);
                acc[ro * 4 + 3] = fmaf(v5, cc, acc[ro * 4 + 3]);
            }
        }
    }
}

__global__ __launch_bounds__(256, 4)
void imagewise_conv2d_kernel(const float* __restrict__ img,
                             const float* __restrict__ ker,
                             float* __restrict__ out) {
    __shared__ float4 wts4[CC * 3];                        // 12 floats / channel (padded)
    __shared__ __align__(16) float tile[STAGES][SM_TILE];  // 3-stage ring (R3 shape)

    const int n     = blockIdx.x;
    const int yt    = blockIdx.y;
    const int tid   = threadIdx.x;
    const int tx    = tid & 31;
    const int ty    = tid >> 5;
    const int x0    = tx * 4;
    const int y0    = ty * 2;
    const int ybase = yt * OUT_ROWS_PER_TILE;

    // ---- stage weights, padded so each channel is 3 float4s ----
    {
        const float* kn = ker + (size_t)n * CC * 9;
        for (int e = tid; e < CC * 9; e += 256) {
            int c = e / 9;
            int i = e - c * 9;
            ((float*)&wts4[c * 3])[i] = kn[e];
        }
    }

    // ---- hoisted copy descriptors (loop-invariant across channels) ----
    int soff0, soff1, soff2 = 0, goff0, goff1, goff2 = 0;
    {
        int r0 = tid >> 5, c40 = (tid & 31) * 4;
        int rg0 = ybase + r0; if (rg0 > HH - 1) rg0 = HH - 1;
        soff0 = r0 * TILE_STRIDE + c40;  goff0 = rg0 * WW + c40;

        int i1 = tid + 256, r1 = i1 >> 5, c41 = (i1 & 31) * 4;
        int rg1 = ybase + r1; if (rg1 > HH - 1) rg1 = HH - 1;
        soff1 = r1 * TILE_STRIDE + c41;  goff1 = rg1 * WW + c41;

        int i2 = tid + 512;
        if (i2 < CP_PER_STAGE) {
            int r2 = i2 >> 5, c42 = (i2 & 31) * 4;
            int rg2 = ybase + r2; if (rg2 > HH - 1) rg2 = HH - 1;
            soff2 = r2 * TILE_STRIDE + c42;  goff2 = rg2 * WW + c42;
        }
    }
    const bool has3 = (tid + 512) < CP_PER_STAGE;   // tid < 64

    const float* imgn = img + (size_t)n * CC * HWSZ;

    auto issue = [&](float* sbase, const float* g) {
        cp_async16(sbase + soff0, g + goff0);
        cp_async16(sbase + soff1, g + goff1);
        if (has3) cp_async16(sbase + soff2, g + goff2);
        cp_commit();
    };

    // ---- prologue: channels 0 and 1 into stages 0 and 1 ----
    const float* src = imgn;
    issue(&tile[0][0], src); src += HWSZ;
    issue(&tile[1][0], src); src += HWSZ;      // src now -> channel 2

    float acc[8];
    #pragma unroll
    for (int i = 0; i < 8; ++i) acc[i] = 0.0f;

    const int yx = y0 * TILE_STRIDE + x0;
    const float4* wp = wts4;
    int cur = 0, nxt = 2;                      // nxt = (cur + 2) % 3

    for (int c = 0; c < CC; ++c) {
        // Wait for channel c's stage (allow one newer group in flight), then sync.
        if (c + 1 < CC) cp_wait1(); else cp_wait0();
        __syncthreads();   // c's data visible; compute of c-1 (stage nxt) done

        // Issue channel c+2 into the stage just freed by c-1.
        if (c + 2 < CC) { issue(&tile[nxt][0], src); src += HWSZ; }

        compute_ch(&tile[cur][yx], wp, acc);
        wp += 3;
        cur = (cur == STAGES - 1) ? 0 : cur + 1;
        nxt = (nxt == STAGES - 1) ? 0 : nxt + 1;
    }

    // ---- store (mask 126-row/col edges) ----
    const int gy0 = ybase + y0;
    #pragma unroll
    for (int ry = 0; ry < 2; ++ry) {
        const int y = gy0 + ry;
        if (y < OH) {
            float* o = out + ((size_t)n * OH + y) * OW + x0;
            #pragma unroll
            for (int xc = 0; xc < 4; ++xc) {
                if (x0 + xc < OW) o[xc] = acc[ry * 4 + xc];
            }
        }
    }
}

extern "C" void kernel_launch(void* const* d_in, const int* in_sizes, int n_in,
                              void* d_out, int out_size) {
    const float* img = (const float*)d_in[0];   // [64,64,128,128] f32
    const float* ker = (const float*)d_in[1];   // [64,64,3,3]     f32
    float* out       = (float*)d_out;           // [64,1,126,126]  f32

    dim3 grid(NN, N_TILES);
    imagewise_conv2d_kernel<<<grid, 256>>>(img, ker, out);
}

// round 6
// speedup vs baseline: 2.0478x; 1.1849x over previous
#include <cuda_runtime.h>

#define NN 64
#define CC 64
#define HH 128
#define WW 128
#define HWSZ (HH * WW)
#define OH 126
#define OW 126
#define OUT_ROWS_PER_TILE 16
#define N_TILES 8
#define TILE_ROWS 18          // 16 output rows + 2 halo
#define TILE_STRIDE 132       // padded row, keeps 16B alignment
#define SM_TILE (TILE_ROWS * TILE_STRIDE)
#define STAGES 3
#define NTHREADS 128
#define CP_PER_STAGE (TILE_ROWS * 32)   // 576 float4 copies

__device__ __forceinline__ void cp_async16(const float* smem, const float* gmem) {
    unsigned saddr = (unsigned)__cvta_generic_to_shared((void*)smem);
    asm volatile("cp.async.cg.shared.global [%0], [%1], 16;\n" :: "r"(saddr), "l"(gmem));
}
__device__ __forceinline__ void cp_commit() {
    asm volatile("cp.async.commit_group;\n" ::: "memory");
}
__device__ __forceinline__ void cp_wait1() {
    asm volatile("cp.async.wait_group 1;\n" ::: "memory");
}
__device__ __forceinline__ void cp_wait0() {
    asm volatile("cp.async.wait_group 0;\n" ::: "memory");
}

// One channel of 3x3 conv on a 4-row x 4-col output patch. Weights packed 3xfloat4.
__device__ __forceinline__ void compute_ch(const float* __restrict__ t,
                                           const float4* __restrict__ w4,
                                           float* __restrict__ acc) {
    const float4 wa = w4[0];
    const float4 wb = w4[1];
    const float w8  = ((const float*)(w4 + 2))[0];
    const float w0 = wa.x, w1 = wa.y, w2 = wa.z, w3 = wa.w;
    const float w4_ = wb.x, w5 = wb.y, w6 = wb.z, w7 = wb.w;

    #pragma unroll
    for (int j = 0; j < 6; ++j) {                 // 6 input rows -> 4 output rows
        const float* row = t + j * TILE_STRIDE;
        const float4 p = *(const float4*)(row);
        const float2 q = *(const float2*)(row + 4);
        const float v0 = p.x, v1 = p.y, v2 = p.z, v3 = p.w, v4 = q.x, v5 = q.y;
        #pragma unroll
        for (int kh = 0; kh < 3; ++kh) {
            const int ro = j - kh;                // compile-time after unroll
            if (ro >= 0 && ro < 4) {
                const float a  = (kh == 0) ? w0 : (kh == 1) ? w3 : w6;
                const float b  = (kh == 0) ? w1 : (kh == 1) ? w4_ : w7;
                const float cc = (kh == 0) ? w2 : (kh == 1) ? w5 : w8;
                acc[ro * 4 + 0] = fmaf(v0, a,  acc[ro * 4 + 0]);
                acc[ro * 4 + 0] = fmaf(v1, b,  acc[ro * 4 + 0]);
                acc[ro * 4 + 0] = fmaf(v2, cc, acc[ro * 4 + 0]);
                acc[ro * 4 + 1] = fmaf(v1, a,  acc[ro * 4 + 1]);
                acc[ro * 4 + 1] = fmaf(v2, b,  acc[ro * 4 + 1]);
                acc[ro * 4 + 1] = fmaf(v3, cc, acc[ro * 4 + 1]);
                acc[ro * 4 + 2] = fmaf(v2, a,  acc[ro * 4 + 2]);
                acc[ro * 4 + 2] = fmaf(v3, b,  acc[ro * 4 + 2]);
                acc[ro * 4 + 2] = fmaf(v4, cc, acc[ro * 4 + 2]);
                acc[ro * 4 + 3] = fmaf(v3, a,  acc[ro * 4 + 3]);
                acc[ro * 4 + 3] = fmaf(v4, b,  acc[ro * 4 + 3]);
                acc[ro * 4 + 3] = fmaf(v5, cc, acc[ro * 4 + 3]);
            }
        }
    }
}

__global__ __launch_bounds__(NTHREADS, 7)
void imagewise_conv2d_kernel(const float* __restrict__ img,
                             const float* __restrict__ ker,
                             float* __restrict__ out) {
    __shared__ float4 wts4[CC * 3];                        // 12 floats / channel (padded)
    __shared__ __align__(16) float tile[STAGES][SM_TILE];  // 3-stage ring

    const int n     = blockIdx.x;
    const int yt    = blockIdx.y;
    const int tid   = threadIdx.x;
    const int tx    = tid & 31;        // 32 col-groups x 4 cols
    const int ty    = tid >> 5;        // 4 row-groups  x 4 rows
    const int x0    = tx * 4;
    const int y0    = ty * 4;
    const int ybase = yt * OUT_ROWS_PER_TILE;

    // ---- stage weights, padded so each channel is 3 float4s ----
    {
        const float* kn = ker + (size_t)n * CC * 9;
        for (int e = tid; e < CC * 9; e += NTHREADS) {
            int c = e / 9;
            int i = e - c * 9;
            ((float*)&wts4[c * 3])[i] = kn[e];
        }
    }

    // ---- hoisted copy descriptors (loop-invariant across channels) ----
    // 576 float4 copies / 128 threads = 4 full rounds + 1 partial (tid < 64).
    int soff[5], goff[5];
    #pragma unroll
    for (int k = 0; k < 5; ++k) {
        int idx = tid + k * NTHREADS;
        if (idx < CP_PER_STAGE) {
            int r  = idx >> 5;
            int c4 = (idx & 31) * 4;
            int rg = ybase + r; if (rg > HH - 1) rg = HH - 1;   // clamp halo
            soff[k] = r * TILE_STRIDE + c4;
            goff[k] = rg * WW + c4;
        } else {
            soff[k] = 0; goff[k] = 0;
        }
    }
    const int  s0 = soff[0], s1 = soff[1], s2 = soff[2], s3 = soff[3], s4 = soff[4];
    const int  g0 = goff[0], g1 = goff[1], g2 = goff[2], g3 = goff[3], g4 = goff[4];
    const bool has5 = (tid + 4 * NTHREADS) < CP_PER_STAGE;   // tid < 64

    const float* imgn = img + (size_t)n * CC * HWSZ;

    auto issue = [&](float* sbase, const float* g) {
        cp_async16(sbase + s0, g + g0);
        cp_async16(sbase + s1, g + g1);
        cp_async16(sbase + s2, g + g2);
        cp_async16(sbase + s3, g + g3);
        if (has5) cp_async16(sbase + s4, g + g4);
        cp_commit();
    };

    // ---- prologue: channels 0 and 1 into stages 0 and 1 ----
    const float* src = imgn;
    issue(&tile[0][0], src); src += HWSZ;
    issue(&tile[1][0], src); src += HWSZ;      // src now -> channel 2

    float acc[16];
    #pragma unroll
    for (int i = 0; i < 16; ++i) acc[i] = 0.0f;

    const int yx = y0 * TILE_STRIDE + x0;
    const float4* wp = wts4;
    int cur = 0, nxt = 2;                      // nxt = (cur + 2) % 3

    for (int c = 0; c < CC; ++c) {
        // Wait for channel c's stage (allow one newer group in flight), then sync.
        if (c + 1 < CC) cp_wait1(); else cp_wait0();
        __syncthreads();   // c's data visible; compute of c-1 (stage nxt) done

        // Issue channel c+2 into the stage just freed by c-1.
        if (c + 2 < CC) { issue(&tile[nxt][0], src); src += HWSZ; }

        compute_ch(&tile[cur][yx], wp, acc);
        wp += 3;
        cur = (cur == STAGES - 1) ? 0 : cur + 1;
        nxt = (nxt == STAGES - 1) ? 0 : nxt + 1;
    }

    // ---- store (mask 126-row/col edges) ----
    const int gy0 = ybase + y0;
    #pragma unroll
    for (int ry = 0; ry < 4; ++ry) {
        const int y = gy0 + ry;
        if (y < OH) {
            float* o = out + ((size_t)n * OH + y) * OW + x0;
            #pragma unroll
            for (int xc = 0; xc < 4; ++xc) {
                if (x0 + xc < OW) o[xc] = acc[ry * 4 + xc];
            }
        }
    }
}

extern "C" void kernel_launch(void* const* d_in, const int* in_sizes, int n_in,
                              void* d_out, int out_size) {
    const float* img = (const float*)d_in[0];   // [64,64,128,128] f32
    const float* ker = (const float*)d_in[1];   // [64,64,3,3]     f32
    float* out       = (float*)d_out;           // [64,1,126,126]  f32

    dim3 grid(NN, N_TILES);
    imagewise_conv2d_kernel<<<grid, NTHREADS>>>(img, ker, out);
}